// round 10
// baseline (speedup 1.0000x reference)
#include <cuda_runtime.h>
#include <cuda_bf16.h>
#include <math.h>

#define HDIM 256
#define BSEG 4096
#define K1   (3 * HDIM)   // 768
#define SPLIT1 8          // gemm1 K-split (768 = 8 x 96)
#define SPLIT2 4          // gemm2 K-split (256 = 4 x 64)

__device__ float g_combined[BSEG * K1];          // [B, 3H]
__device__ float g_part[SPLIT1 * BSEG * HDIM];   // split-K partials (32 MB)
__device__ float g_hidden[BSEG * HDIM];          // [B, H]

__device__ __forceinline__ int lower_bound_i32(const int* __restrict__ a,
                                               int n, int v) {
    int lo = 0, hi = n;
    while (lo < hi) {
        int mid = (lo + hi) >> 1;
        if (a[mid] < v) lo = mid + 1; else hi = mid;
    }
    return lo;
}

__device__ __forceinline__ void acc4(float4& s, float4& m, const float4 v) {
    s.x += v.x; s.y += v.y; s.z += v.z; s.w += v.w;
    m.x = fmaxf(m.x, v.x); m.y = fmaxf(m.y, v.y);
    m.z = fmaxf(m.z, v.z); m.w = fmaxf(m.w, v.w);
}

// ---------------------------------------------------------------------------
// Stage 1: segment pooling (R6/R7 proven version: MLP=4, 171us @ 76.7% DRAM).
// ---------------------------------------------------------------------------
__global__ void __launch_bounds__(256)
pool_kernel(const float4* __restrict__ feat4,
            const int* __restrict__ batch,
            float4* __restrict__ combined4,
            int n_rows) {
    const int b = blockIdx.x;
    const int t = threadIdx.x;
    const int g = t >> 6;
    const int c = t & 63;

    __shared__ int s_se[2];
    if (t < 2) s_se[t] = lower_bound_i32(batch, n_rows, b + t);
    __syncthreads();
    const int start = s_se[0];
    const int end   = s_se[1];
    const int cnt   = end - start;

    float4 s0 = make_float4(0.f, 0.f, 0.f, 0.f), s1 = s0;
    float4 m0 = make_float4(-INFINITY, -INFINITY, -INFINITY, -INFINITY);
    float4 m1 = m0;

    int i = start + g;
    for (; i + 12 < end; i += 16) {
        float4 v0 = __ldcs(&feat4[(size_t)(i +  0) * 64 + c]);
        float4 v1 = __ldcs(&feat4[(size_t)(i +  4) * 64 + c]);
        float4 v2 = __ldcs(&feat4[(size_t)(i +  8) * 64 + c]);
        float4 v3 = __ldcs(&feat4[(size_t)(i + 12) * 64 + c]);
        acc4(s0, m0, v0); acc4(s1, m1, v1);
        acc4(s0, m0, v2); acc4(s1, m1, v3);
    }
    for (; i < end; i += 4) {
        float4 v = __ldcs(&feat4[(size_t)i * 64 + c]);
        acc4(s0, m0, v);
    }
    float4 s = make_float4(s0.x + s1.x, s0.y + s1.y, s0.z + s1.z, s0.w + s1.w);
    float4 m = make_float4(fmaxf(m0.x, m1.x), fmaxf(m0.y, m1.y),
                           fmaxf(m0.z, m1.z), fmaxf(m0.w, m1.w));

    __shared__ float4 red_s[4][64];
    __shared__ float4 red_m[4][64];
    red_s[g][c] = s;
    red_m[g][c] = m;
    __syncthreads();

    if (t < 64) {
        float4 S = red_s[0][t], M = red_m[0][t];
        #pragma unroll
        for (int gg = 1; gg < 4; ++gg) {
            float4 ps = red_s[gg][t], pm = red_m[gg][t];
            S.x += ps.x; S.y += ps.y; S.z += ps.z; S.w += ps.w;
            M.x = fmaxf(M.x, pm.x); M.y = fmaxf(M.y, pm.y);
            M.z = fmaxf(M.z, pm.z); M.w = fmaxf(M.w, pm.w);
        }
        float inv = (cnt > 0) ? (1.0f / (float)cnt) : 0.0f;
        if (cnt == 0) { S = make_float4(0.f, 0.f, 0.f, 0.f); M = S; }
        float4 mean = make_float4(S.x * inv, S.y * inv, S.z * inv, S.w * inv);
        float4* row = combined4 + (size_t)b * 192;
        row[t]       = mean;
        row[64 + t]  = S;
        row[128 + t] = M;
    }
}

// ---------------------------------------------------------------------------
// Split-K GEMM: R7 tile structure + register-pipelined fragments.
// BM=64, BN=64, BK=32, 256 threads, 4x4 f32x2 microtile.
// ---------------------------------------------------------------------------
__device__ __forceinline__ unsigned long long pack2(float x) {
    unsigned long long r;
    asm("mov.b64 %0, {%1, %1};" : "=l"(r) : "f"(x));
    return r;
}
#define FFMA2(acc, a, b) \
    asm("fma.rn.f32x2 %0, %1, %2, %0;" : "+l"(acc) : "l"(a), "l"(b))

__global__ void __launch_bounds__(256)
gemm_splitk(const float* __restrict__ A,
            const float* __restrict__ W,
            float* __restrict__ Cpart,
            int M, int K, int N, int k_chunk) {
    __shared__ float As[2][32][68];
    __shared__ float Bs[2][32][64];

    const int tid = threadIdx.x;
    const int tx  = tid & 15;
    const int ty  = tid >> 4;
    const int bm  = blockIdx.y * 64;
    const int bn  = blockIdx.x * 64;
    const int kb  = blockIdx.z * k_chunk;

    const int la0_r = tid >> 3,          la0_c = (tid & 7) * 4;
    const int la1_r = (tid + 256) >> 3,  la1_c = ((tid + 256) & 7) * 4;
    const int lb0_r = tid >> 4,          lb0_n = (tid & 15) * 4;
    const int lb1_r = (tid + 256) >> 4,  lb1_n = ((tid + 256) & 15) * 4;

    const int nk = k_chunk >> 5;
    float4 a0, a1, w0, w1;

    a0 = *(const float4*)&A[(size_t)(bm + la0_r) * K + kb + la0_c];
    a1 = *(const float4*)&A[(size_t)(bm + la1_r) * K + kb + la1_c];
    w0 = *(const float4*)&W[(size_t)(kb + lb0_r) * N + bn + lb0_n];
    w1 = *(const float4*)&W[(size_t)(kb + lb1_r) * N + bn + lb1_n];

    As[0][la0_c + 0][la0_r] = a0.x; As[0][la0_c + 1][la0_r] = a0.y;
    As[0][la0_c + 2][la0_r] = a0.z; As[0][la0_c + 3][la0_r] = a0.w;
    As[0][la1_c + 0][la1_r] = a1.x; As[0][la1_c + 1][la1_r] = a1.y;
    As[0][la1_c + 2][la1_r] = a1.z; As[0][la1_c + 3][la1_r] = a1.w;
    *(float4*)&Bs[0][lb0_r][lb0_n] = w0;
    *(float4*)&Bs[0][lb1_r][lb1_n] = w1;
    __syncthreads();

    unsigned long long acc2[4][2] = {};

    for (int kk = 0; kk < nk; ++kk) {
        const int buf = kk & 1;
        if (kk + 1 < nk) {
            const int k0 = kb + ((kk + 1) << 5);
            a0 = *(const float4*)&A[(size_t)(bm + la0_r) * K + k0 + la0_c];
            a1 = *(const float4*)&A[(size_t)(bm + la1_r) * K + k0 + la1_c];
            w0 = *(const float4*)&W[(size_t)(k0 + lb0_r) * N + bn + lb0_n];
            w1 = *(const float4*)&W[(size_t)(k0 + lb1_r) * N + bn + lb1_n];
        }

        // Register-pipelined fragment loop: prefetch frag k+1 during FFMAs of k.
        float4     av = *(const float4*)&As[buf][0][ty * 4];
        ulonglong2 bp = *(const ulonglong2*)&Bs[buf][0][tx * 4];
        #pragma unroll
        for (int k = 0; k < 32; ++k) {
            float4     av_n;
            ulonglong2 bp_n;
            if (k < 31) {
                av_n = *(const float4*)&As[buf][k + 1][ty * 4];
                bp_n = *(const ulonglong2*)&Bs[buf][k + 1][tx * 4];
            }
            const unsigned long long ap0 = pack2(av.x);
            const unsigned long long ap1 = pack2(av.y);
            const unsigned long long ap2 = pack2(av.z);
            const unsigned long long ap3 = pack2(av.w);
            FFMA2(acc2[0][0], ap0, bp.x); FFMA2(acc2[0][1], ap0, bp.y);
            FFMA2(acc2[1][0], ap1, bp.x); FFMA2(acc2[1][1], ap1, bp.y);
            FFMA2(acc2[2][0], ap2, bp.x); FFMA2(acc2[2][1], ap2, bp.y);
            FFMA2(acc2[3][0], ap3, bp.x); FFMA2(acc2[3][1], ap3, bp.y);
            if (k < 31) { av = av_n; bp = bp_n; }
        }

        if (kk + 1 < nk) {
            const int nb = buf ^ 1;
            As[nb][la0_c + 0][la0_r] = a0.x; As[nb][la0_c + 1][la0_r] = a0.y;
            As[nb][la0_c + 2][la0_r] = a0.z; As[nb][la0_c + 3][la0_r] = a0.w;
            As[nb][la1_c + 0][la1_r] = a1.x; As[nb][la1_c + 1][la1_r] = a1.y;
            As[nb][la1_c + 2][la1_r] = a1.z; As[nb][la1_c + 3][la1_r] = a1.w;
            *(float4*)&Bs[nb][lb0_r][lb0_n] = w0;
            *(float4*)&Bs[nb][lb1_r][lb1_n] = w1;
            __syncthreads();
        }
    }

    float* Cp = Cpart + (size_t)blockIdx.z * M * N;
    #pragma unroll
    for (int iu = 0; iu < 4; ++iu) {
        const int m = bm + ty * 4 + iu;
        float x0, x1, x2, x3;
        asm("mov.b64 {%0, %1}, %2;" : "=f"(x0), "=f"(x1) : "l"(acc2[iu][0]));
        asm("mov.b64 {%0, %1}, %2;" : "=f"(x2), "=f"(x3) : "l"(acc2[iu][1]));
        *(float4*)&Cp[(size_t)m * N + bn + tx * 4] = make_float4(x0, x1, x2, x3);
    }
}

// ---------------------------------------------------------------------------
// Epilogue: out = (sum over parts) + bias, optional SiLU.
// ---------------------------------------------------------------------------
__global__ void __launch_bounds__(256)
epilogue(const float4* __restrict__ Cpart,
         const float4* __restrict__ bias4,
         float4* __restrict__ out4,
         int total4, int parts, int n4, int do_silu) {
    const int idx = blockIdx.x * 256 + threadIdx.x;
    if (idx >= total4) return;
    float4 s = Cpart[idx];
    #pragma unroll 4
    for (int p = 1; p < parts; ++p) {
        const float4 v = __ldcs(&Cpart[(size_t)p * total4 + idx]);
        s.x += v.x; s.y += v.y; s.z += v.z; s.w += v.w;
    }
    const float4 bv = bias4[idx & (n4 - 1)];
    s.x += bv.x; s.y += bv.y; s.z += bv.z; s.w += bv.w;
    if (do_silu) {
        s.x = s.x / (1.0f + __expf(-s.x));
        s.y = s.y / (1.0f + __expf(-s.y));
        s.z = s.z / (1.0f + __expf(-s.z));
        s.w = s.w / (1.0f + __expf(-s.w));
    }
    out4[idx] = s;
}

// ---------------------------------------------------------------------------
extern "C" void kernel_launch(void* const* d_in, const int* in_sizes, int n_in,
                              void* d_out, int out_size) {
    const float* feat  = (const float*)d_in[0];
    const int*   batch = (const int*)d_in[1];
    const float* W1    = (const float*)d_in[2];
    const float* b1    = (const float*)d_in[3];
    const float* W2    = (const float*)d_in[4];
    const float* b2    = (const float*)d_in[5];
    float*       out   = (float*)d_out;

    const int n_rows = in_sizes[1];

    float *combined, *part, *hidden;
    cudaGetSymbolAddress((void**)&combined, g_combined);
    cudaGetSymbolAddress((void**)&part,     g_part);
    cudaGetSymbolAddress((void**)&hidden,   g_hidden);

    pool_kernel<<<BSEG, 256>>>((const float4*)feat, batch,
                               (float4*)combined, n_rows);

    const int total4 = BSEG * HDIM / 4;   // 262144
    const int n4 = HDIM / 4;              // 64

    dim3 g1(HDIM / 64, BSEG / 64, SPLIT1);   // (4, 64, 8) = 2048 CTAs
    gemm_splitk<<<g1, 256>>>(combined, W1, part, BSEG, K1, HDIM, K1 / SPLIT1);
    epilogue<<<(total4 + 255) / 256, 256>>>((const float4*)part,
                                            (const float4*)b1,
                                            (float4*)hidden,
                                            total4, SPLIT1, n4, 1);

    dim3 g2(HDIM / 64, BSEG / 64, SPLIT2);   // (4, 64, 4) = 1024 CTAs
    gemm_splitk<<<g2, 256>>>(hidden, W2, part, BSEG, HDIM, HDIM, HDIM / SPLIT2);
    epilogue<<<(total4 + 255) / 256, 256>>>((const float4*)part,
                                            (const float4*)b2,
                                            (float4*)out,
                                            total4, SPLIT2, n4, 0);
}

// round 11
// speedup vs baseline: 1.2193x; 1.2193x over previous
#include <cuda_runtime.h>
#include <cuda_bf16.h>
#include <math.h>

#define HDIM 256
#define BSEG 4096
#define K1   (3 * HDIM)   // 768
#define SPLIT1 4          // gemm1 K-split (768 = 4 x 192)
#define SPLIT2 2          // gemm2 K-split (256 = 2 x 128)

#define CHUNK      256
#define SLOTS      6                 // max segments overlapping one chunk
#define NCHUNK_MAX 4103              // ceil(1.05e6 / 256)

__device__ float g_psum[NCHUNK_MAX * SLOTS * HDIM];   // per-(chunk,slot) sums
__device__ float g_pmax[NCHUNK_MAX * SLOTS * HDIM];   // per-(chunk,slot) maxes
__device__ float g_combined[BSEG * K1];               // [B, 3H]
__device__ float g_part[SPLIT1 * BSEG * HDIM];        // split-K partials
__device__ float g_hidden[BSEG * HDIM];               // [B, H]

__device__ __forceinline__ int lower_bound_i32(const int* __restrict__ a,
                                               int n, int v) {
    int lo = 0, hi = n;
    while (lo < hi) {
        int mid = (lo + hi) >> 1;
        if (a[mid] < v) lo = mid + 1; else hi = mid;
    }
    return lo;
}

__device__ __forceinline__ void acc4(float4& s, float4& m, const float4 v) {
    s.x += v.x; s.y += v.y; s.z += v.z; s.w += v.w;
    m.x = fmaxf(m.x, v.x); m.y = fmaxf(m.y, v.y);
    m.z = fmaxf(m.z, v.z); m.w = fmaxf(m.w, v.w);
}

// ---------------------------------------------------------------------------
// Stage 1a: fixed-size chunk pooling — perfectly balanced blocks.
// Block c reduces rows [256c, 256c+256) split by segment boundaries found via
// a cooperative scan of the (sorted) batch values. Partials per (chunk, slot).
// ---------------------------------------------------------------------------
__global__ void __launch_bounds__(256)
pool_chunk(const float4* __restrict__ feat4,   // [N, 64] float4
           const int* __restrict__ batch,
           float4* __restrict__ psum4,         // [NCHUNK, SLOTS, 64] float4
           float4* __restrict__ pmax4,
           int n_rows) {
    const int chunk = blockIdx.x;
    const int r0 = chunk * CHUNK;
    const int r1 = min(r0 + CHUNK, n_rows);
    const int len = r1 - r0;
    const int t = threadIdx.x;
    const int g = t >> 6;
    const int lane = t & 63;

    __shared__ int sb[SLOTS + 1];
    __shared__ int s_first, s_nseg;
    if (t <= SLOTS) sb[t] = len;
    __syncthreads();
    if (t == 0) {
        s_first = batch[r0];
        s_nseg  = batch[r1 - 1] - s_first + 1;
        sb[0] = 0;
    }
    __syncthreads();
    const int seg_first = s_first;

    // boundary scan: thread t checks for a step at row r0+t
    if (t > 0 && t < len) {
        const int v = batch[r0 + t];
        const int p = batch[r0 + t - 1];
        if (v != p) {
            const int j = v - seg_first;   // >= 1
            if (j < SLOTS) sb[j] = t;
        }
    }
    __syncthreads();
    const int nseg = min(s_nseg, SLOTS);

    __shared__ float4 red_s[4][64];
    __shared__ float4 red_m[4][64];

    for (int j = 0; j < nseg; ++j) {
        const int a = r0 + sb[j];
        const int b = r0 + sb[j + 1];

        float4 s0 = make_float4(0.f, 0.f, 0.f, 0.f), s1 = s0;
        float4 m0 = make_float4(-INFINITY, -INFINITY, -INFINITY, -INFINITY);
        float4 m1 = m0;

        int i = a + g;
        for (; i + 12 < b; i += 16) {
            float4 v0 = __ldcs(&feat4[(size_t)(i +  0) * 64 + lane]);
            float4 v1 = __ldcs(&feat4[(size_t)(i +  4) * 64 + lane]);
            float4 v2 = __ldcs(&feat4[(size_t)(i +  8) * 64 + lane]);
            float4 v3 = __ldcs(&feat4[(size_t)(i + 12) * 64 + lane]);
            acc4(s0, m0, v0); acc4(s1, m1, v1);
            acc4(s0, m0, v2); acc4(s1, m1, v3);
        }
        for (; i < b; i += 4) {
            float4 v = __ldcs(&feat4[(size_t)i * 64 + lane]);
            acc4(s0, m0, v);
        }
        float4 s = make_float4(s0.x + s1.x, s0.y + s1.y,
                               s0.z + s1.z, s0.w + s1.w);
        float4 m = make_float4(fmaxf(m0.x, m1.x), fmaxf(m0.y, m1.y),
                               fmaxf(m0.z, m1.z), fmaxf(m0.w, m1.w));

        red_s[g][lane] = s;
        red_m[g][lane] = m;
        __syncthreads();

        if (t < 64) {
            float4 S = red_s[0][t], M = red_m[0][t];
            #pragma unroll
            for (int gg = 1; gg < 4; ++gg) {
                float4 ps = red_s[gg][t], pm = red_m[gg][t];
                S.x += ps.x; S.y += ps.y; S.z += ps.z; S.w += ps.w;
                M.x = fmaxf(M.x, pm.x); M.y = fmaxf(M.y, pm.y);
                M.z = fmaxf(M.z, pm.z); M.w = fmaxf(M.w, pm.w);
            }
            const size_t off = ((size_t)chunk * SLOTS + j) * 64 + t;
            psum4[off] = S;
            pmax4[off] = M;
        }
        __syncthreads();
    }
}

// ---------------------------------------------------------------------------
// Stage 1b: per-segment combine of chunk partials -> combined [B, 3H].
// Segment b overlaps chunks [start/256, (end-1)/256] (2-3 chunks typically).
// ---------------------------------------------------------------------------
__global__ void __launch_bounds__(256)
pool_finalize(const int* __restrict__ batch,
              const float4* __restrict__ psum4,
              const float4* __restrict__ pmax4,
              float4* __restrict__ combined4,    // [B, 192] float4
              int n_rows) {
    const int t = threadIdx.x;
    const int seg = blockIdx.x * 4 + (t >> 6);
    const int lane = t & 63;

    __shared__ int bounds[5];
    if (t < 5) bounds[t] = lower_bound_i32(batch, n_rows, blockIdx.x * 4 + t);
    __syncthreads();
    const int start = bounds[t >> 6];
    const int end   = bounds[(t >> 6) + 1];
    const int cnt   = end - start;

    float4 S = make_float4(0.f, 0.f, 0.f, 0.f);
    float4 M = make_float4(-INFINITY, -INFINITY, -INFINITY, -INFINITY);

    if (cnt > 0) {
        const int c0 = start >> 8;
        const int c1 = (end - 1) >> 8;
        for (int c = c0; c <= c1; ++c) {
            const int j = seg - batch[c << 8];
            if (j >= 0 && j < SLOTS) {
                const size_t off = ((size_t)c * SLOTS + j) * 64 + lane;
                const float4 ps = psum4[off];
                const float4 pm = pmax4[off];
                S.x += ps.x; S.y += ps.y; S.z += ps.z; S.w += ps.w;
                M.x = fmaxf(M.x, pm.x); M.y = fmaxf(M.y, pm.y);
                M.z = fmaxf(M.z, pm.z); M.w = fmaxf(M.w, pm.w);
            }
        }
    } else {
        M = make_float4(0.f, 0.f, 0.f, 0.f);
    }

    const float inv = (cnt > 0) ? (1.0f / (float)cnt) : 0.0f;
    const float4 mean = make_float4(S.x * inv, S.y * inv, S.z * inv, S.w * inv);
    float4* row = combined4 + (size_t)seg * 192;
    row[lane]       = mean;
    row[64 + lane]  = S;
    row[128 + lane] = M;
}

// ---------------------------------------------------------------------------
// Split-K GEMM (exact R7 version — measured best; do not touch).
// BM=64, BN=64, BK=32, 256 threads, 4x4 f32x2 microtile.
// ---------------------------------------------------------------------------
__device__ __forceinline__ unsigned long long pack2(float x) {
    unsigned long long r;
    asm("mov.b64 %0, {%1, %1};" : "=l"(r) : "f"(x));
    return r;
}
#define FFMA2(acc, a, b) \
    asm("fma.rn.f32x2 %0, %1, %2, %0;" : "+l"(acc) : "l"(a), "l"(b))

__global__ void __launch_bounds__(256)
gemm_splitk(const float* __restrict__ A,
            const float* __restrict__ W,
            float* __restrict__ Cpart,
            int M, int K, int N, int k_chunk) {
    __shared__ float As[2][32][68];
    __shared__ float Bs[2][32][64];

    const int tid = threadIdx.x;
    const int tx  = tid & 15;
    const int ty  = tid >> 4;
    const int bm  = blockIdx.y * 64;
    const int bn  = blockIdx.x * 64;
    const int kb  = blockIdx.z * k_chunk;

    const int la0_r = tid >> 3,          la0_c = (tid & 7) * 4;
    const int la1_r = (tid + 256) >> 3,  la1_c = ((tid + 256) & 7) * 4;
    const int lb0_r = tid >> 4,          lb0_n = (tid & 15) * 4;
    const int lb1_r = (tid + 256) >> 4,  lb1_n = ((tid + 256) & 15) * 4;

    const int nk = k_chunk >> 5;
    float4 a0, a1, w0, w1;

    a0 = *(const float4*)&A[(size_t)(bm + la0_r) * K + kb + la0_c];
    a1 = *(const float4*)&A[(size_t)(bm + la1_r) * K + kb + la1_c];
    w0 = *(const float4*)&W[(size_t)(kb + lb0_r) * N + bn + lb0_n];
    w1 = *(const float4*)&W[(size_t)(kb + lb1_r) * N + bn + lb1_n];

    As[0][la0_c + 0][la0_r] = a0.x; As[0][la0_c + 1][la0_r] = a0.y;
    As[0][la0_c + 2][la0_r] = a0.z; As[0][la0_c + 3][la0_r] = a0.w;
    As[0][la1_c + 0][la1_r] = a1.x; As[0][la1_c + 1][la1_r] = a1.y;
    As[0][la1_c + 2][la1_r] = a1.z; As[0][la1_c + 3][la1_r] = a1.w;
    *(float4*)&Bs[0][lb0_r][lb0_n] = w0;
    *(float4*)&Bs[0][lb1_r][lb1_n] = w1;
    __syncthreads();

    unsigned long long acc2[4][2] = {};

    for (int kk = 0; kk < nk; ++kk) {
        const int buf = kk & 1;
        if (kk + 1 < nk) {
            const int k0 = kb + ((kk + 1) << 5);
            a0 = *(const float4*)&A[(size_t)(bm + la0_r) * K + k0 + la0_c];
            a1 = *(const float4*)&A[(size_t)(bm + la1_r) * K + k0 + la1_c];
            w0 = *(const float4*)&W[(size_t)(k0 + lb0_r) * N + bn + lb0_n];
            w1 = *(const float4*)&W[(size_t)(k0 + lb1_r) * N + bn + lb1_n];
        }

        #pragma unroll
        for (int k = 0; k < 32; ++k) {
            const float4 av = *(const float4*)&As[buf][k][ty * 4];
            const ulonglong2 bp = *(const ulonglong2*)&Bs[buf][k][tx * 4];
            const unsigned long long ap0 = pack2(av.x);
            const unsigned long long ap1 = pack2(av.y);
            const unsigned long long ap2 = pack2(av.z);
            const unsigned long long ap3 = pack2(av.w);
            FFMA2(acc2[0][0], ap0, bp.x); FFMA2(acc2[0][1], ap0, bp.y);
            FFMA2(acc2[1][0], ap1, bp.x); FFMA2(acc2[1][1], ap1, bp.y);
            FFMA2(acc2[2][0], ap2, bp.x); FFMA2(acc2[2][1], ap2, bp.y);
            FFMA2(acc2[3][0], ap3, bp.x); FFMA2(acc2[3][1], ap3, bp.y);
        }

        if (kk + 1 < nk) {
            const int nb = buf ^ 1;
            As[nb][la0_c + 0][la0_r] = a0.x; As[nb][la0_c + 1][la0_r] = a0.y;
            As[nb][la0_c + 2][la0_r] = a0.z; As[nb][la0_c + 3][la0_r] = a0.w;
            As[nb][la1_c + 0][la1_r] = a1.x; As[nb][la1_c + 1][la1_r] = a1.y;
            As[nb][la1_c + 2][la1_r] = a1.z; As[nb][la1_c + 3][la1_r] = a1.w;
            *(float4*)&Bs[nb][lb0_r][lb0_n] = w0;
            *(float4*)&Bs[nb][lb1_r][lb1_n] = w1;
            __syncthreads();
        }
    }

    float* Cp = Cpart + (size_t)blockIdx.z * M * N;
    #pragma unroll
    for (int iu = 0; iu < 4; ++iu) {
        const int m = bm + ty * 4 + iu;
        float x0, x1, x2, x3;
        asm("mov.b64 {%0, %1}, %2;" : "=f"(x0), "=f"(x1) : "l"(acc2[iu][0]));
        asm("mov.b64 {%0, %1}, %2;" : "=f"(x2), "=f"(x3) : "l"(acc2[iu][1]));
        *(float4*)&Cp[(size_t)m * N + bn + tx * 4] = make_float4(x0, x1, x2, x3);
    }
}

// ---------------------------------------------------------------------------
// Epilogue: out = (sum over parts) + bias, optional SiLU.
// ---------------------------------------------------------------------------
__global__ void __launch_bounds__(256)
epilogue(const float4* __restrict__ Cpart,
         const float4* __restrict__ bias4,
         float4* __restrict__ out4,
         int total4, int parts, int n4, int do_silu) {
    const int idx = blockIdx.x * 256 + threadIdx.x;
    if (idx >= total4) return;
    float4 s = Cpart[idx];
    for (int p = 1; p < parts; ++p) {
        const float4 v = Cpart[(size_t)p * total4 + idx];
        s.x += v.x; s.y += v.y; s.z += v.z; s.w += v.w;
    }
    const float4 bv = bias4[idx & (n4 - 1)];
    s.x += bv.x; s.y += bv.y; s.z += bv.z; s.w += bv.w;
    if (do_silu) {
        s.x = s.x / (1.0f + __expf(-s.x));
        s.y = s.y / (1.0f + __expf(-s.y));
        s.z = s.z / (1.0f + __expf(-s.z));
        s.w = s.w / (1.0f + __expf(-s.w));
    }
    out4[idx] = s;
}

// ---------------------------------------------------------------------------
extern "C" void kernel_launch(void* const* d_in, const int* in_sizes, int n_in,
                              void* d_out, int out_size) {
    const float* feat  = (const float*)d_in[0];
    const int*   batch = (const int*)d_in[1];
    const float* W1    = (const float*)d_in[2];
    const float* b1    = (const float*)d_in[3];
    const float* W2    = (const float*)d_in[4];
    const float* b2    = (const float*)d_in[5];
    float*       out   = (float*)d_out;

    const int n_rows = in_sizes[1];
    const int n_chunks = (n_rows + CHUNK - 1) / CHUNK;

    float *psum, *pmax, *combined, *part, *hidden;
    cudaGetSymbolAddress((void**)&psum,     g_psum);
    cudaGetSymbolAddress((void**)&pmax,     g_pmax);
    cudaGetSymbolAddress((void**)&combined, g_combined);
    cudaGetSymbolAddress((void**)&part,     g_part);
    cudaGetSymbolAddress((void**)&hidden,   g_hidden);

    pool_chunk<<<n_chunks, 256>>>((const float4*)feat, batch,
                                  (float4*)psum, (float4*)pmax, n_rows);
    pool_finalize<<<BSEG / 4, 256>>>(batch, (const float4*)psum,
                                     (const float4*)pmax,
                                     (float4*)combined, n_rows);

    const int total4 = BSEG * HDIM / 4;   // 262144
    const int n4 = HDIM / 4;              // 64

    dim3 g1(HDIM / 64, BSEG / 64, SPLIT1);
    gemm_splitk<<<g1, 256>>>(combined, W1, part, BSEG, K1, HDIM, K1 / SPLIT1);
    epilogue<<<(total4 + 255) / 256, 256>>>((const float4*)part,
                                            (const float4*)b1,
                                            (float4*)hidden,
                                            total4, SPLIT1, n4, 1);

    dim3 g2(HDIM / 64, BSEG / 64, SPLIT2);
    gemm_splitk<<<g2, 256>>>(hidden, W2, part, BSEG, HDIM, HDIM, HDIM / SPLIT2);
    epilogue<<<(total4 + 255) / 256, 256>>>((const float4*)part,
                                            (const float4*)b2,
                                            (float4*)out,
                                            total4, SPLIT2, n4, 0);
}

// round 12
// speedup vs baseline: 1.2561x; 1.0302x over previous
#include <cuda_runtime.h>
#include <cuda_bf16.h>
#include <math.h>

#define HDIM 256
#define BSEG 4096
#define K1   (3 * HDIM)   // 768
#define SPLIT1 4          // gemm1 K-split (768 = 4 x 192)
#define SPLIT2 4          // gemm2 K-split (256 = 4 x 64)

__device__ float g_combined[BSEG * K1];          // [B, 3H]
__device__ float g_part[SPLIT1 * BSEG * HDIM];   // split-K partials
__device__ float g_hidden[BSEG * HDIM];          // [B, H]

__device__ __forceinline__ int lower_bound_i32(const int* __restrict__ a,
                                               int n, int v) {
    int lo = 0, hi = n;
    while (lo < hi) {
        int mid = (lo + hi) >> 1;
        if (a[mid] < v) lo = mid + 1; else hi = mid;
    }
    return lo;
}

__device__ __forceinline__ void acc4(float4& s, float4& m, const float4 v) {
    s.x += v.x; s.y += v.y; s.z += v.z; s.w += v.w;
    m.x = fmaxf(m.x, v.x); m.y = fmaxf(m.y, v.y);
    m.z = fmaxf(m.z, v.z); m.w = fmaxf(m.w, v.w);
}

// ---------------------------------------------------------------------------
// Stage 1: segment pooling (R7 proven version: MLP=4, 171us @ 76.7% DRAM).
// ---------------------------------------------------------------------------
__global__ void __launch_bounds__(256)
pool_kernel(const float4* __restrict__ feat4,
            const int* __restrict__ batch,
            float4* __restrict__ combined4,
            int n_rows) {
    const int b = blockIdx.x;
    const int t = threadIdx.x;
    const int g = t >> 6;
    const int c = t & 63;

    __shared__ int s_se[2];
    if (t < 2) s_se[t] = lower_bound_i32(batch, n_rows, b + t);
    __syncthreads();
    const int start = s_se[0];
    const int end   = s_se[1];
    const int cnt   = end - start;

    float4 s0 = make_float4(0.f, 0.f, 0.f, 0.f), s1 = s0;
    float4 m0 = make_float4(-INFINITY, -INFINITY, -INFINITY, -INFINITY);
    float4 m1 = m0;

    int i = start + g;
    for (; i + 12 < end; i += 16) {
        float4 v0 = __ldcs(&feat4[(size_t)(i +  0) * 64 + c]);
        float4 v1 = __ldcs(&feat4[(size_t)(i +  4) * 64 + c]);
        float4 v2 = __ldcs(&feat4[(size_t)(i +  8) * 64 + c]);
        float4 v3 = __ldcs(&feat4[(size_t)(i + 12) * 64 + c]);
        acc4(s0, m0, v0); acc4(s1, m1, v1);
        acc4(s0, m0, v2); acc4(s1, m1, v3);
    }
    for (; i < end; i += 4) {
        float4 v = __ldcs(&feat4[(size_t)i * 64 + c]);
        acc4(s0, m0, v);
    }
    float4 s = make_float4(s0.x + s1.x, s0.y + s1.y, s0.z + s1.z, s0.w + s1.w);
    float4 m = make_float4(fmaxf(m0.x, m1.x), fmaxf(m0.y, m1.y),
                           fmaxf(m0.z, m1.z), fmaxf(m0.w, m1.w));

    __shared__ float4 red_s[4][64];
    __shared__ float4 red_m[4][64];
    red_s[g][c] = s;
    red_m[g][c] = m;
    __syncthreads();

    if (t < 64) {
        float4 S = red_s[0][t], M = red_m[0][t];
        #pragma unroll
        for (int gg = 1; gg < 4; ++gg) {
            float4 ps = red_s[gg][t], pm = red_m[gg][t];
            S.x += ps.x; S.y += ps.y; S.z += ps.z; S.w += ps.w;
            M.x = fmaxf(M.x, pm.x); M.y = fmaxf(M.y, pm.y);
            M.z = fmaxf(M.z, pm.z); M.w = fmaxf(M.w, pm.w);
        }
        float inv = (cnt > 0) ? (1.0f / (float)cnt) : 0.0f;
        if (cnt == 0) { S = make_float4(0.f, 0.f, 0.f, 0.f); M = S; }
        float4 mean = make_float4(S.x * inv, S.y * inv, S.z * inv, S.w * inv);
        float4* row = combined4 + (size_t)b * 192;
        row[t]       = mean;
        row[64 + t]  = S;
        row[128 + t] = M;
    }
}

// ---------------------------------------------------------------------------
// Split-K GEMM (exact R7 version — measured best; unchanged).
// BM=64, BN=64, BK=32, 256 threads, 4x4 f32x2 microtile.
// ---------------------------------------------------------------------------
__device__ __forceinline__ unsigned long long pack2(float x) {
    unsigned long long r;
    asm("mov.b64 %0, {%1, %1};" : "=l"(r) : "f"(x));
    return r;
}
#define FFMA2(acc, a, b) \
    asm("fma.rn.f32x2 %0, %1, %2, %0;" : "+l"(acc) : "l"(a), "l"(b))

__global__ void __launch_bounds__(256)
gemm_splitk(const float* __restrict__ A,
            const float* __restrict__ W,
            float* __restrict__ Cpart,
            int M, int K, int N, int k_chunk) {
    __shared__ float As[2][32][68];
    __shared__ float Bs[2][32][64];

    const int tid = threadIdx.x;
    const int tx  = tid & 15;
    const int ty  = tid >> 4;
    const int bm  = blockIdx.y * 64;
    const int bn  = blockIdx.x * 64;
    const int kb  = blockIdx.z * k_chunk;

    const int la0_r = tid >> 3,          la0_c = (tid & 7) * 4;
    const int la1_r = (tid + 256) >> 3,  la1_c = ((tid + 256) & 7) * 4;
    const int lb0_r = tid >> 4,          lb0_n = (tid & 15) * 4;
    const int lb1_r = (tid + 256) >> 4,  lb1_n = ((tid + 256) & 15) * 4;

    const int nk = k_chunk >> 5;
    float4 a0, a1, w0, w1;

    a0 = *(const float4*)&A[(size_t)(bm + la0_r) * K + kb + la0_c];
    a1 = *(const float4*)&A[(size_t)(bm + la1_r) * K + kb + la1_c];
    w0 = *(const float4*)&W[(size_t)(kb + lb0_r) * N + bn + lb0_n];
    w1 = *(const float4*)&W[(size_t)(kb + lb1_r) * N + bn + lb1_n];

    As[0][la0_c + 0][la0_r] = a0.x; As[0][la0_c + 1][la0_r] = a0.y;
    As[0][la0_c + 2][la0_r] = a0.z; As[0][la0_c + 3][la0_r] = a0.w;
    As[0][la1_c + 0][la1_r] = a1.x; As[0][la1_c + 1][la1_r] = a1.y;
    As[0][la1_c + 2][la1_r] = a1.z; As[0][la1_c + 3][la1_r] = a1.w;
    *(float4*)&Bs[0][lb0_r][lb0_n] = w0;
    *(float4*)&Bs[0][lb1_r][lb1_n] = w1;
    __syncthreads();

    unsigned long long acc2[4][2] = {};

    for (int kk = 0; kk < nk; ++kk) {
        const int buf = kk & 1;
        if (kk + 1 < nk) {
            const int k0 = kb + ((kk + 1) << 5);
            a0 = *(const float4*)&A[(size_t)(bm + la0_r) * K + k0 + la0_c];
            a1 = *(const float4*)&A[(size_t)(bm + la1_r) * K + k0 + la1_c];
            w0 = *(const float4*)&W[(size_t)(k0 + lb0_r) * N + bn + lb0_n];
            w1 = *(const float4*)&W[(size_t)(k0 + lb1_r) * N + bn + lb1_n];
        }

        #pragma unroll
        for (int k = 0; k < 32; ++k) {
            const float4 av = *(const float4*)&As[buf][k][ty * 4];
            const ulonglong2 bp = *(const ulonglong2*)&Bs[buf][k][tx * 4];
            const unsigned long long ap0 = pack2(av.x);
            const unsigned long long ap1 = pack2(av.y);
            const unsigned long long ap2 = pack2(av.z);
            const unsigned long long ap3 = pack2(av.w);
            FFMA2(acc2[0][0], ap0, bp.x); FFMA2(acc2[0][1], ap0, bp.y);
            FFMA2(acc2[1][0], ap1, bp.x); FFMA2(acc2[1][1], ap1, bp.y);
            FFMA2(acc2[2][0], ap2, bp.x); FFMA2(acc2[2][1], ap2, bp.y);
            FFMA2(acc2[3][0], ap3, bp.x); FFMA2(acc2[3][1], ap3, bp.y);
        }

        if (kk + 1 < nk) {
            const int nb = buf ^ 1;
            As[nb][la0_c + 0][la0_r] = a0.x; As[nb][la0_c + 1][la0_r] = a0.y;
            As[nb][la0_c + 2][la0_r] = a0.z; As[nb][la0_c + 3][la0_r] = a0.w;
            As[nb][la1_c + 0][la1_r] = a1.x; As[nb][la1_c + 1][la1_r] = a1.y;
            As[nb][la1_c + 2][la1_r] = a1.z; As[nb][la1_c + 3][la1_r] = a1.w;
            *(float4*)&Bs[nb][lb0_r][lb0_n] = w0;
            *(float4*)&Bs[nb][lb1_r][lb1_n] = w1;
            __syncthreads();
        }
    }

    float* Cp = Cpart + (size_t)blockIdx.z * M * N;
    #pragma unroll
    for (int iu = 0; iu < 4; ++iu) {
        const int m = bm + ty * 4 + iu;
        float x0, x1, x2, x3;
        asm("mov.b64 {%0, %1}, %2;" : "=f"(x0), "=f"(x1) : "l"(acc2[iu][0]));
        asm("mov.b64 {%0, %1}, %2;" : "=f"(x2), "=f"(x3) : "l"(acc2[iu][1]));
        *(float4*)&Cp[(size_t)m * N + bn + tx * 4] = make_float4(x0, x1, x2, x3);
    }
}

// ---------------------------------------------------------------------------
// Epilogue v2: 2 float4 per thread, all part-loads issued upfront (MLP=8).
// out = (sum over parts) + bias, optional SiLU.
// ---------------------------------------------------------------------------
__global__ void __launch_bounds__(256)
epilogue(const float4* __restrict__ Cpart,
         const float4* __restrict__ bias4,
         float4* __restrict__ out4,
         int total4, int parts, int n4, int do_silu) {
    const int idx = (blockIdx.x * 256 + threadIdx.x) * 2;
    if (idx + 1 >= total4 + 1) return;  // total4 is even; idx+1 < total4 holds

    float4 s0 = __ldcs(&Cpart[idx]);
    float4 s1 = __ldcs(&Cpart[idx + 1]);
    #pragma unroll 4
    for (int p = 1; p < parts; ++p) {
        const float4 v0 = __ldcs(&Cpart[(size_t)p * total4 + idx]);
        const float4 v1 = __ldcs(&Cpart[(size_t)p * total4 + idx + 1]);
        s0.x += v0.x; s0.y += v0.y; s0.z += v0.z; s0.w += v0.w;
        s1.x += v1.x; s1.y += v1.y; s1.z += v1.z; s1.w += v1.w;
    }
    const float4 b0 = bias4[idx & (n4 - 1)];
    const float4 b1 = bias4[(idx + 1) & (n4 - 1)];
    s0.x += b0.x; s0.y += b0.y; s0.z += b0.z; s0.w += b0.w;
    s1.x += b1.x; s1.y += b1.y; s1.z += b1.z; s1.w += b1.w;
    if (do_silu) {
        s0.x = s0.x / (1.0f + __expf(-s0.x));
        s0.y = s0.y / (1.0f + __expf(-s0.y));
        s0.z = s0.z / (1.0f + __expf(-s0.z));
        s0.w = s0.w / (1.0f + __expf(-s0.w));
        s1.x = s1.x / (1.0f + __expf(-s1.x));
        s1.y = s1.y / (1.0f + __expf(-s1.y));
        s1.z = s1.z / (1.0f + __expf(-s1.z));
        s1.w = s1.w / (1.0f + __expf(-s1.w));
    }
    out4[idx]     = s0;
    out4[idx + 1] = s1;
}

// ---------------------------------------------------------------------------
extern "C" void kernel_launch(void* const* d_in, const int* in_sizes, int n_in,
                              void* d_out, int out_size) {
    const float* feat  = (const float*)d_in[0];
    const int*   batch = (const int*)d_in[1];
    const float* W1    = (const float*)d_in[2];
    const float* b1    = (const float*)d_in[3];
    const float* W2    = (const float*)d_in[4];
    const float* b2    = (const float*)d_in[5];
    float*       out   = (float*)d_out;

    const int n_rows = in_sizes[1];

    float *combined, *part, *hidden;
    cudaGetSymbolAddress((void**)&combined, g_combined);
    cudaGetSymbolAddress((void**)&part,     g_part);
    cudaGetSymbolAddress((void**)&hidden,   g_hidden);

    pool_kernel<<<BSEG, 256>>>((const float4*)feat, batch,
                               (float4*)combined, n_rows);

    const int total4 = BSEG * HDIM / 4;           // 262144
    const int n4 = HDIM / 4;                      // 64
    const int epi_blocks = total4 / 2 / 256;      // 512

    dim3 g1(HDIM / 64, BSEG / 64, SPLIT1);        // (4, 64, 4) = 1024 CTAs
    gemm_splitk<<<g1, 256>>>(combined, W1, part, BSEG, K1, HDIM, K1 / SPLIT1);
    epilogue<<<epi_blocks, 256>>>((const float4*)part, (const float4*)b1,
                                  (float4*)hidden, total4, SPLIT1, n4, 1);

    dim3 g2(HDIM / 64, BSEG / 64, SPLIT2);        // (4, 64, 4) = 1024 CTAs
    gemm_splitk<<<g2, 256>>>(hidden, W2, part, BSEG, HDIM, HDIM, HDIM / SPLIT2);
    epilogue<<<epi_blocks, 256>>>((const float4*)part, (const float4*)b2,
                                  (float4*)out, total4, SPLIT2, n4, 0);
}

// round 13
// speedup vs baseline: 1.2594x; 1.0026x over previous
#include <cuda_runtime.h>
#include <cuda_bf16.h>
#include <math.h>

#define HDIM 256
#define BSEG 4096
#define K1   (3 * HDIM)   // 768
#define SPLIT1 4          // gemm1 K-split (768 = 4 x 192)
#define SPLIT2 4          // gemm2 K-split (256 = 4 x 64)

__device__ float g_combined[BSEG * K1];          // [B, 3H]
__device__ float g_part[SPLIT1 * BSEG * HDIM];   // split-K partials
__device__ float g_hidden[BSEG * HDIM];          // [B, H]

__device__ __forceinline__ int lower_bound_i32(const int* __restrict__ a,
                                               int n, int v) {
    int lo = 0, hi = n;
    while (lo < hi) {
        int mid = (lo + hi) >> 1;
        if (a[mid] < v) lo = mid + 1; else hi = mid;
    }
    return lo;
}

__device__ __forceinline__ void acc4(float4& s, float4& m, const float4 v) {
    s.x += v.x; s.y += v.y; s.z += v.z; s.w += v.w;
    m.x = fmaxf(m.x, v.x); m.y = fmaxf(m.y, v.y);
    m.z = fmaxf(m.z, v.z); m.w = fmaxf(m.w, v.w);
}

// ---------------------------------------------------------------------------
// Stage 1: column-split segment pooling.
// Block blk = 2*b + h reduces segment b, float4 columns [32h, 32h+32).
// 128 threads = 4 row-groups x 32 lanes; MLP=4; direct writes (no partials).
// ---------------------------------------------------------------------------
__global__ void __launch_bounds__(128)
pool_kernel(const float4* __restrict__ feat4,   // [N, 64] float4
            const int* __restrict__ batch,
            float4* __restrict__ combined4,     // [B, 192] float4 (mean|sum|max)
            int n_rows) {
    const int blk = blockIdx.x;
    const int b = blk >> 1;
    const int h = blk & 1;
    const int t = threadIdx.x;
    const int g = t >> 5;             // 0..3 row-group
    const int lane = t & 31;          // 0..31
    const int col = (h << 5) + lane;  // float4 column 0..63

    __shared__ int s_se[2];
    if (t < 2) s_se[t] = lower_bound_i32(batch, n_rows, b + t);
    __syncthreads();
    const int start = s_se[0];
    const int end   = s_se[1];
    const int cnt   = end - start;

    float4 s0 = make_float4(0.f, 0.f, 0.f, 0.f), s1 = s0;
    float4 m0 = make_float4(-INFINITY, -INFINITY, -INFINITY, -INFINITY);
    float4 m1 = m0;

    int i = start + g;
    for (; i + 12 < end; i += 16) {
        float4 v0 = __ldcs(&feat4[(size_t)(i +  0) * 64 + col]);
        float4 v1 = __ldcs(&feat4[(size_t)(i +  4) * 64 + col]);
        float4 v2 = __ldcs(&feat4[(size_t)(i +  8) * 64 + col]);
        float4 v3 = __ldcs(&feat4[(size_t)(i + 12) * 64 + col]);
        acc4(s0, m0, v0); acc4(s1, m1, v1);
        acc4(s0, m0, v2); acc4(s1, m1, v3);
    }
    for (; i < end; i += 4) {
        float4 v = __ldcs(&feat4[(size_t)i * 64 + col]);
        acc4(s0, m0, v);
    }
    float4 s = make_float4(s0.x + s1.x, s0.y + s1.y, s0.z + s1.z, s0.w + s1.w);
    float4 m = make_float4(fmaxf(m0.x, m1.x), fmaxf(m0.y, m1.y),
                           fmaxf(m0.z, m1.z), fmaxf(m0.w, m1.w));

    __shared__ float4 red_s[4][32];
    __shared__ float4 red_m[4][32];
    red_s[g][lane] = s;
    red_m[g][lane] = m;
    __syncthreads();

    if (t < 32) {
        float4 S = red_s[0][t], M = red_m[0][t];
        #pragma unroll
        for (int gg = 1; gg < 4; ++gg) {
            float4 ps = red_s[gg][t], pm = red_m[gg][t];
            S.x += ps.x; S.y += ps.y; S.z += ps.z; S.w += ps.w;
            M.x = fmaxf(M.x, pm.x); M.y = fmaxf(M.y, pm.y);
            M.z = fmaxf(M.z, pm.z); M.w = fmaxf(M.w, pm.w);
        }
        float inv = (cnt > 0) ? (1.0f / (float)cnt) : 0.0f;
        if (cnt == 0) { S = make_float4(0.f, 0.f, 0.f, 0.f); M = S; }
        float4 mean = make_float4(S.x * inv, S.y * inv, S.z * inv, S.w * inv);
        const int L = (h << 5) + t;   // float4 column within H
        float4* row = combined4 + (size_t)b * 192;
        row[L]       = mean;
        row[64 + L]  = S;
        row[128 + L] = M;
    }
}

// ---------------------------------------------------------------------------
// Split-K GEMM (exact R7/R12 version — measured best; unchanged).
// BM=64, BN=64, BK=32, 256 threads, 4x4 f32x2 microtile.
// ---------------------------------------------------------------------------
__device__ __forceinline__ unsigned long long pack2(float x) {
    unsigned long long r;
    asm("mov.b64 %0, {%1, %1};" : "=l"(r) : "f"(x));
    return r;
}
#define FFMA2(acc, a, b) \
    asm("fma.rn.f32x2 %0, %1, %2, %0;" : "+l"(acc) : "l"(a), "l"(b))

__global__ void __launch_bounds__(256)
gemm_splitk(const float* __restrict__ A,
            const float* __restrict__ W,
            float* __restrict__ Cpart,
            int M, int K, int N, int k_chunk) {
    __shared__ float As[2][32][68];
    __shared__ float Bs[2][32][64];

    const int tid = threadIdx.x;
    const int tx  = tid & 15;
    const int ty  = tid >> 4;
    const int bm  = blockIdx.y * 64;
    const int bn  = blockIdx.x * 64;
    const int kb  = blockIdx.z * k_chunk;

    const int la0_r = tid >> 3,          la0_c = (tid & 7) * 4;
    const int la1_r = (tid + 256) >> 3,  la1_c = ((tid + 256) & 7) * 4;
    const int lb0_r = tid >> 4,          lb0_n = (tid & 15) * 4;
    const int lb1_r = (tid + 256) >> 4,  lb1_n = ((tid + 256) & 15) * 4;

    const int nk = k_chunk >> 5;
    float4 a0, a1, w0, w1;

    a0 = *(const float4*)&A[(size_t)(bm + la0_r) * K + kb + la0_c];
    a1 = *(const float4*)&A[(size_t)(bm + la1_r) * K + kb + la1_c];
    w0 = *(const float4*)&W[(size_t)(kb + lb0_r) * N + bn + lb0_n];
    w1 = *(const float4*)&W[(size_t)(kb + lb1_r) * N + bn + lb1_n];

    As[0][la0_c + 0][la0_r] = a0.x; As[0][la0_c + 1][la0_r] = a0.y;
    As[0][la0_c + 2][la0_r] = a0.z; As[0][la0_c + 3][la0_r] = a0.w;
    As[0][la1_c + 0][la1_r] = a1.x; As[0][la1_c + 1][la1_r] = a1.y;
    As[0][la1_c + 2][la1_r] = a1.z; As[0][la1_c + 3][la1_r] = a1.w;
    *(float4*)&Bs[0][lb0_r][lb0_n] = w0;
    *(float4*)&Bs[0][lb1_r][lb1_n] = w1;
    __syncthreads();

    unsigned long long acc2[4][2] = {};

    for (int kk = 0; kk < nk; ++kk) {
        const int buf = kk & 1;
        if (kk + 1 < nk) {
            const int k0 = kb + ((kk + 1) << 5);
            a0 = *(const float4*)&A[(size_t)(bm + la0_r) * K + k0 + la0_c];
            a1 = *(const float4*)&A[(size_t)(bm + la1_r) * K + k0 + la1_c];
            w0 = *(const float4*)&W[(size_t)(k0 + lb0_r) * N + bn + lb0_n];
            w1 = *(const float4*)&W[(size_t)(k0 + lb1_r) * N + bn + lb1_n];
        }

        #pragma unroll
        for (int k = 0; k < 32; ++k) {
            const float4 av = *(const float4*)&As[buf][k][ty * 4];
            const ulonglong2 bp = *(const ulonglong2*)&Bs[buf][k][tx * 4];
            const unsigned long long ap0 = pack2(av.x);
            const unsigned long long ap1 = pack2(av.y);
            const unsigned long long ap2 = pack2(av.z);
            const unsigned long long ap3 = pack2(av.w);
            FFMA2(acc2[0][0], ap0, bp.x); FFMA2(acc2[0][1], ap0, bp.y);
            FFMA2(acc2[1][0], ap1, bp.x); FFMA2(acc2[1][1], ap1, bp.y);
            FFMA2(acc2[2][0], ap2, bp.x); FFMA2(acc2[2][1], ap2, bp.y);
            FFMA2(acc2[3][0], ap3, bp.x); FFMA2(acc2[3][1], ap3, bp.y);
        }

        if (kk + 1 < nk) {
            const int nb = buf ^ 1;
            As[nb][la0_c + 0][la0_r] = a0.x; As[nb][la0_c + 1][la0_r] = a0.y;
            As[nb][la0_c + 2][la0_r] = a0.z; As[nb][la0_c + 3][la0_r] = a0.w;
            As[nb][la1_c + 0][la1_r] = a1.x; As[nb][la1_c + 1][la1_r] = a1.y;
            As[nb][la1_c + 2][la1_r] = a1.z; As[nb][la1_c + 3][la1_r] = a1.w;
            *(float4*)&Bs[nb][lb0_r][lb0_n] = w0;
            *(float4*)&Bs[nb][lb1_r][lb1_n] = w1;
            __syncthreads();
        }
    }

    float* Cp = Cpart + (size_t)blockIdx.z * M * N;
    #pragma unroll
    for (int iu = 0; iu < 4; ++iu) {
        const int m = bm + ty * 4 + iu;
        float x0, x1, x2, x3;
        asm("mov.b64 {%0, %1}, %2;" : "=f"(x0), "=f"(x1) : "l"(acc2[iu][0]));
        asm("mov.b64 {%0, %1}, %2;" : "=f"(x2), "=f"(x3) : "l"(acc2[iu][1]));
        *(float4*)&Cp[(size_t)m * N + bn + tx * 4] = make_float4(x0, x1, x2, x3);
    }
}

// ---------------------------------------------------------------------------
// Epilogue: 2 float4 per thread (MLP up to 8); sum parts + bias (+SiLU).
// ---------------------------------------------------------------------------
__global__ void __launch_bounds__(256)
epilogue(const float4* __restrict__ Cpart,
         const float4* __restrict__ bias4,
         float4* __restrict__ out4,
         int total4, int parts, int n4, int do_silu) {
    const int idx = (blockIdx.x * 256 + threadIdx.x) * 2;
    if (idx >= total4) return;

    float4 s0 = __ldcs(&Cpart[idx]);
    float4 s1 = __ldcs(&Cpart[idx + 1]);
    #pragma unroll 4
    for (int p = 1; p < parts; ++p) {
        const float4 v0 = __ldcs(&Cpart[(size_t)p * total4 + idx]);
        const float4 v1 = __ldcs(&Cpart[(size_t)p * total4 + idx + 1]);
        s0.x += v0.x; s0.y += v0.y; s0.z += v0.z; s0.w += v0.w;
        s1.x += v1.x; s1.y += v1.y; s1.z += v1.z; s1.w += v1.w;
    }
    const float4 b0 = bias4[idx & (n4 - 1)];
    const float4 b1 = bias4[(idx + 1) & (n4 - 1)];
    s0.x += b0.x; s0.y += b0.y; s0.z += b0.z; s0.w += b0.w;
    s1.x += b1.x; s1.y += b1.y; s1.z += b1.z; s1.w += b1.w;
    if (do_silu) {
        s0.x = s0.x / (1.0f + __expf(-s0.x));
        s0.y = s0.y / (1.0f + __expf(-s0.y));
        s0.z = s0.z / (1.0f + __expf(-s0.z));
        s0.w = s0.w / (1.0f + __expf(-s0.w));
        s1.x = s1.x / (1.0f + __expf(-s1.x));
        s1.y = s1.y / (1.0f + __expf(-s1.y));
        s1.z = s1.z / (1.0f + __expf(-s1.z));
        s1.w = s1.w / (1.0f + __expf(-s1.w));
    }
    out4[idx]     = s0;
    out4[idx + 1] = s1;
}

// ---------------------------------------------------------------------------
extern "C" void kernel_launch(void* const* d_in, const int* in_sizes, int n_in,
                              void* d_out, int out_size) {
    const float* feat  = (const float*)d_in[0];
    const int*   batch = (const int*)d_in[1];
    const float* W1    = (const float*)d_in[2];
    const float* b1    = (const float*)d_in[3];
    const float* W2    = (const float*)d_in[4];
    const float* b2    = (const float*)d_in[5];
    float*       out   = (float*)d_out;

    const int n_rows = in_sizes[1];

    float *combined, *part, *hidden;
    cudaGetSymbolAddress((void**)&combined, g_combined);
    cudaGetSymbolAddress((void**)&part,     g_part);
    cudaGetSymbolAddress((void**)&hidden,   g_hidden);

    pool_kernel<<<2 * BSEG, 128>>>((const float4*)feat, batch,
                                   (float4*)combined, n_rows);

    const int total4 = BSEG * HDIM / 4;           // 262144
    const int n4 = HDIM / 4;                      // 64
    const int epi_blocks = total4 / 2 / 256;      // 512

    dim3 g1(HDIM / 64, BSEG / 64, SPLIT1);        // (4, 64, 4) = 1024 CTAs
    gemm_splitk<<<g1, 256>>>(combined, W1, part, BSEG, K1, HDIM, K1 / SPLIT1);
    epilogue<<<epi_blocks, 256>>>((const float4*)part, (const float4*)b1,
                                  (float4*)hidden, total4, SPLIT1, n4, 1);

    dim3 g2(HDIM / 64, BSEG / 64, SPLIT2);        // (4, 64, 4) = 1024 CTAs
    gemm_splitk<<<g2, 256>>>(hidden, W2, part, BSEG, HDIM, HDIM, HDIM / SPLIT2);
    epilogue<<<epi_blocks, 256>>>((const float4*)part, (const float4*)b2,
                                  (float4*)out, total4, SPLIT2, n4, 0);
}